// round 1
// baseline (speedup 1.0000x reference)
#include <cuda_runtime.h>
#include <cuda_bf16.h>

#define BB   2
#define SS   2048
#define DIMM 4096
#define NHH  32
#define NKVV 8
#define HDD  128

// Scratch (device globals; no allocation allowed)
__device__ float g_q[BB * SS * NHH * HDD];   // (b,s,h,hd)
__device__ float g_k[BB * SS * NKVV * HDD];  // (b,s,hk,hd)
__device__ float g_v[BB * SS * NKVV * HDD];
__device__ float g_o[BB * SS * NHH * HDD];   // attention out, (b,s,h,hd)

// ---------------------------------------------------------------------------
// C[M,N] = A[M,K] @ B[N,K]^T   (both row-major, K-contiguous)
// BM=BN=128, BK=16, 256 threads, 8x8 micro-tile. M,N,K all divide evenly.
// ---------------------------------------------------------------------------
__global__ __launch_bounds__(256) void gemm_nt(const float* __restrict__ A,
                                               const float* __restrict__ Bw,
                                               float* __restrict__ C,
                                               int M, int N, int K)
{
    __shared__ float As[16][128];
    __shared__ float Bs[16][128];

    const int tid = threadIdx.x;
    const int tx = tid & 15;
    const int ty = tid >> 4;
    const int m0 = blockIdx.y * 128;
    const int n0 = blockIdx.x * 128;

    float acc[8][8];
#pragma unroll
    for (int r = 0; r < 8; r++)
#pragma unroll
        for (int c = 0; c < 8; c++) acc[r][c] = 0.0f;

    const int lrow = tid >> 2;        // 0..63
    const int lcol = (tid & 3) * 4;   // 0,4,8,12

    for (int k0 = 0; k0 < K; k0 += 16) {
#pragma unroll
        for (int i = 0; i < 2; i++) {
            int row = lrow + i * 64;
            float4 a = *(const float4*)(A + (size_t)(m0 + row) * K + k0 + lcol);
            As[lcol + 0][row] = a.x;
            As[lcol + 1][row] = a.y;
            As[lcol + 2][row] = a.z;
            As[lcol + 3][row] = a.w;
            float4 b = *(const float4*)(Bw + (size_t)(n0 + row) * K + k0 + lcol);
            Bs[lcol + 0][row] = b.x;
            Bs[lcol + 1][row] = b.y;
            Bs[lcol + 2][row] = b.z;
            Bs[lcol + 3][row] = b.w;
        }
        __syncthreads();

#pragma unroll
        for (int kk = 0; kk < 16; kk++) {
            float a[8], b[8];
            *(float4*)&a[0] = *(const float4*)&As[kk][8 * ty];
            *(float4*)&a[4] = *(const float4*)&As[kk][8 * ty + 4];
            *(float4*)&b[0] = *(const float4*)&Bs[kk][8 * tx];
            *(float4*)&b[4] = *(const float4*)&Bs[kk][8 * tx + 4];
#pragma unroll
            for (int r = 0; r < 8; r++)
#pragma unroll
                for (int c = 0; c < 8; c++)
                    acc[r][c] = fmaf(a[r], b[c], acc[r][c]);
        }
        __syncthreads();
    }

#pragma unroll
    for (int r = 0; r < 8; r++) {
        float* cp = C + (size_t)(m0 + 8 * ty + r) * N + n0 + 8 * tx;
        *(float4*)cp       = make_float4(acc[r][0], acc[r][1], acc[r][2], acc[r][3]);
        *(float4*)(cp + 4) = make_float4(acc[r][4], acc[r][5], acc[r][6], acc[r][7]);
    }
}

// ---------------------------------------------------------------------------
// RoPE, in place. x layout: (b, s, nh, HD). total = B*S*nh*64 pair-ids.
// ---------------------------------------------------------------------------
__global__ void rope_kernel(float* __restrict__ x, const float* __restrict__ fc,
                            const float* __restrict__ fs, int nh, int total)
{
    int idx = blockIdx.x * blockDim.x + threadIdx.x;
    if (idx >= total) return;
    int i  = idx & 63;          // pair index within head dim
    int th = idx >> 6;          // (b*S + s)*nh + h
    int s  = (th / nh) % SS;
    float c  = fc[s * 64 + i];
    float sn = fs[s * 64 + i];
    float* p = x + (size_t)th * HDD + 2 * i;
    float xr = p[0], xi = p[1];
    p[0] = xr * c - xi * sn;
    p[1] = xr * sn + xi * c;
}

// ---------------------------------------------------------------------------
// Flash attention (causal, GQA). 64 q-rows per CTA, 256 threads.
// smem: Qt[128][68] (d-major, pre-scaled), Kt[128][68], Vs[64][128], Ps[64][68]
// ---------------------------------------------------------------------------
#define FLASH_SMEM ((128 * 68 + 128 * 68 + 64 * 128 + 64 * 68) * 4)

__global__ __launch_bounds__(256) void flash_kernel()
{
    extern __shared__ float sm[];
    float* Qt = sm;                  // [128][68]
    float* Kt = Qt + 128 * 68;       // [128][68]
    float* Vs = Kt + 128 * 68;       // [64][128]
    float* Ps = Vs + 64 * 128;       // [64][68]

    const int tid = threadIdx.x;
    const int tx = tid & 15;         // score cols 4*tx..+3 ; O cols 8*tx..+7
    const int ty = tid >> 4;         // rows 4*ty..+3
    const int qt = blockIdx.x;
    const int h  = blockIdx.y;
    const int b  = blockIdx.z;
    const int hk = h >> 2;           // NH/NKV = 4
    const int q0 = qt * 64;
    const float scale = 0.08838834764831845f;  // 1/sqrt(128)

    // Load Q tile (scaled), transpose into Qt[d][row]
    const float* qg = g_q + (((size_t)(b * SS + q0)) * NHH + h) * HDD;
    for (int f = tid; f < 64 * 32; f += 256) {
        int row = f >> 5;
        int d   = (f & 31) * 4;
        float4 v = *(const float4*)(qg + (size_t)row * (NHH * HDD) + d);
        Qt[(d + 0) * 68 + row] = v.x * scale;
        Qt[(d + 1) * 68 + row] = v.y * scale;
        Qt[(d + 2) * 68 + row] = v.z * scale;
        Qt[(d + 3) * 68 + row] = v.w * scale;
    }

    float m[4], l[4], o[4][8];
#pragma unroll
    for (int r = 0; r < 4; r++) {
        m[r] = -1e30f;
        l[r] = 0.0f;
#pragma unroll
        for (int c = 0; c < 8; c++) o[r][c] = 0.0f;
    }

    const float* kg = g_k + ((size_t)(b * SS) * NKVV + hk) * HDD;
    const float* vg = g_v + ((size_t)(b * SS) * NKVV + hk) * HDD;

    for (int kt = 0; kt <= qt; kt++) {
        __syncthreads();  // previous iter done with Kt/Vs/Ps
        int k0 = kt * 64;
        for (int f = tid; f < 64 * 32; f += 256) {
            int row = f >> 5;
            int d   = (f & 31) * 4;
            float4 kv = *(const float4*)(kg + (size_t)(k0 + row) * (NKVV * HDD) + d);
            Kt[(d + 0) * 68 + row] = kv.x;
            Kt[(d + 1) * 68 + row] = kv.y;
            Kt[(d + 2) * 68 + row] = kv.z;
            Kt[(d + 3) * 68 + row] = kv.w;
            float4 vv = *(const float4*)(vg + (size_t)(k0 + row) * (NKVV * HDD) + d);
            *(float4*)&Vs[row * 128 + d] = vv;
        }
        __syncthreads();

        // S = Q K^T (Q pre-scaled)
        float s4[4][4];
#pragma unroll
        for (int r = 0; r < 4; r++)
#pragma unroll
            for (int c = 0; c < 4; c++) s4[r][c] = 0.0f;

        for (int d = 0; d < 128; d++) {
            float4 qv = *(const float4*)&Qt[d * 68 + 4 * ty];
            float4 kv = *(const float4*)&Kt[d * 68 + 4 * tx];
            float qa[4] = {qv.x, qv.y, qv.z, qv.w};
            float ka[4] = {kv.x, kv.y, kv.z, kv.w};
#pragma unroll
            for (int r = 0; r < 4; r++)
#pragma unroll
                for (int c = 0; c < 4; c++)
                    s4[r][c] = fmaf(qa[r], ka[c], s4[r][c]);
        }

        if (kt == qt) {
#pragma unroll
            for (int r = 0; r < 4; r++)
#pragma unroll
                for (int c = 0; c < 4; c++)
                    if (4 * tx + c > 4 * ty + r) s4[r][c] = -1e30f;
        }

        // Online softmax update (row reduction across the 16 tx lanes)
#pragma unroll
        for (int r = 0; r < 4; r++) {
            float mx = fmaxf(fmaxf(s4[r][0], s4[r][1]), fmaxf(s4[r][2], s4[r][3]));
#pragma unroll
            for (int off = 8; off > 0; off >>= 1)
                mx = fmaxf(mx, __shfl_xor_sync(0xffffffffu, mx, off, 16));
            float mn    = fmaxf(m[r], mx);
            float alpha = __expf(m[r] - mn);
            float rs = 0.0f;
#pragma unroll
            for (int c = 0; c < 4; c++) {
                s4[r][c] = __expf(s4[r][c] - mn);
                rs += s4[r][c];
            }
#pragma unroll
            for (int off = 8; off > 0; off >>= 1)
                rs += __shfl_xor_sync(0xffffffffu, rs, off, 16);
            l[r] = l[r] * alpha + rs;
            m[r] = mn;
#pragma unroll
            for (int c = 0; c < 8; c++) o[r][c] *= alpha;
            *(float4*)&Ps[(4 * ty + r) * 68 + 4 * tx] =
                make_float4(s4[r][0], s4[r][1], s4[r][2], s4[r][3]);
        }
        __syncthreads();

        // O += P @ V
        for (int j = 0; j < 64; j++) {
            float4 v0 = *(const float4*)&Vs[j * 128 + 8 * tx];
            float4 v1 = *(const float4*)&Vs[j * 128 + 8 * tx + 4];
            float va[8] = {v0.x, v0.y, v0.z, v0.w, v1.x, v1.y, v1.z, v1.w};
            float p0 = Ps[(4 * ty + 0) * 68 + j];
            float p1 = Ps[(4 * ty + 1) * 68 + j];
            float p2 = Ps[(4 * ty + 2) * 68 + j];
            float p3 = Ps[(4 * ty + 3) * 68 + j];
#pragma unroll
            for (int c = 0; c < 8; c++) {
                o[0][c] = fmaf(p0, va[c], o[0][c]);
                o[1][c] = fmaf(p1, va[c], o[1][c]);
                o[2][c] = fmaf(p2, va[c], o[2][c]);
                o[3][c] = fmaf(p3, va[c], o[3][c]);
            }
        }
    }

    // Normalize and store (b, s, h, hd)
#pragma unroll
    for (int r = 0; r < 4; r++) {
        float inv = 1.0f / l[r];
        float* op = g_o + (((size_t)(b * SS + q0 + 4 * ty + r)) * NHH + h) * HDD + 8 * tx;
        *(float4*)op =
            make_float4(o[r][0] * inv, o[r][1] * inv, o[r][2] * inv, o[r][3] * inv);
        *(float4*)(op + 4) =
            make_float4(o[r][4] * inv, o[r][5] * inv, o[r][6] * inv, o[r][7] * inv);
    }
}

// ---------------------------------------------------------------------------
extern "C" void kernel_launch(void* const* d_in, const int* in_sizes, int n_in,
                              void* d_out, int out_size)
{
    const float* x  = (const float*)d_in[0];
    const float* wq = (const float*)d_in[1];
    const float* wk = (const float*)d_in[2];
    const float* wv = (const float*)d_in[3];
    const float* wo = (const float*)d_in[4];
    const float* fc = (const float*)d_in[5];
    const float* fs = (const float*)d_in[6];
    float* out = (float*)d_out;

    float *qp, *kp, *vp, *op;
    cudaGetSymbolAddress((void**)&qp, g_q);
    cudaGetSymbolAddress((void**)&kp, g_k);
    cudaGetSymbolAddress((void**)&vp, g_v);
    cudaGetSymbolAddress((void**)&op, g_o);

    const int M = BB * SS;  // 4096

    // QKV projections
    gemm_nt<<<dim3((NHH * HDD) / 128, M / 128), 256>>>(x, wq, qp, M, NHH * HDD, DIMM);
    gemm_nt<<<dim3((NKVV * HDD) / 128, M / 128), 256>>>(x, wk, kp, M, NKVV * HDD, DIMM);
    gemm_nt<<<dim3((NKVV * HDD) / 128, M / 128), 256>>>(x, wv, vp, M, NKVV * HDD, DIMM);

    // RoPE
    int tq = BB * SS * NHH * 64;
    rope_kernel<<<(tq + 255) / 256, 256>>>(qp, fc, fs, NHH, tq);
    int tk = BB * SS * NKVV * 64;
    rope_kernel<<<(tk + 255) / 256, 256>>>(kp, fc, fs, NKVV, tk);

    // Flash attention
    cudaFuncSetAttribute(flash_kernel, cudaFuncAttributeMaxDynamicSharedMemorySize,
                         FLASH_SMEM);
    flash_kernel<<<dim3(SS / 64, NHH, BB), 256, FLASH_SMEM>>>();

    // Output projection
    gemm_nt<<<dim3(DIMM / 128, M / 128), 256>>>(op, wo, out, M, DIMM, DIMM);
}

// round 4
// speedup vs baseline: 1.4572x; 1.4572x over previous
#include <cuda_runtime.h>
#include <cuda_bf16.h>
#include <cstdint>

#define BB   2
#define SS   2048
#define DIMM 4096
#define NHH  32
#define NKVV 8
#define HDD  128

// ---------------------------------------------------------------------------
// Scratch (device globals; no allocation allowed)
// ---------------------------------------------------------------------------
__device__ float g_q[BB * SS * NHH * HDD];   // (b,s,h,hd)
__device__ float g_k[BB * SS * NKVV * HDD];  // (b,s,hk,hd)
__device__ float g_v[BB * SS * NKVV * HDD];
__device__ float g_o[BB * SS * NHH * HDD];   // attention out, (b,s,h,hd)

// bf16 split (hi/lo) buffers
__device__ __align__(16) __nv_bfloat16 g_xh[4096 * 4096];
__device__ __align__(16) __nv_bfloat16 g_xl[4096 * 4096];
__device__ __align__(16) __nv_bfloat16 g_wqh[4096 * 4096];
__device__ __align__(16) __nv_bfloat16 g_wql[4096 * 4096];
__device__ __align__(16) __nv_bfloat16 g_wkh[1024 * 4096];
__device__ __align__(16) __nv_bfloat16 g_wkl[1024 * 4096];
__device__ __align__(16) __nv_bfloat16 g_wvh[1024 * 4096];
__device__ __align__(16) __nv_bfloat16 g_wvl[1024 * 4096];
__device__ __align__(16) __nv_bfloat16 g_woh[4096 * 4096];
__device__ __align__(16) __nv_bfloat16 g_wol[4096 * 4096];
__device__ __align__(16) __nv_bfloat16 g_oh[4096 * 4096];
__device__ __align__(16) __nv_bfloat16 g_ol[4096 * 4096];

// ---------------------------------------------------------------------------
__device__ __forceinline__ uint32_t smem_u32(const void* p) {
    uint32_t a;
    asm("{ .reg .u64 t; cvta.to.shared.u64 t, %1; cvt.u32.u64 %0, t; }"
        : "=r"(a) : "l"(p));
    return a;
}

__device__ __forceinline__ void mma16816(float* c, const uint32_t* a,
                                         const uint32_t* b) {
    asm volatile(
        "mma.sync.aligned.m16n8k16.row.col.f32.bf16.bf16.f32 "
        "{%0,%1,%2,%3}, {%4,%5,%6,%7}, {%8,%9}, {%0,%1,%2,%3};"
        : "+f"(c[0]), "+f"(c[1]), "+f"(c[2]), "+f"(c[3])
        : "r"(a[0]), "r"(a[1]), "r"(a[2]), "r"(a[3]), "r"(b[0]), "r"(b[1]));
}

// ---------------------------------------------------------------------------
// Split fp32 -> bf16 hi + bf16 lo
// ---------------------------------------------------------------------------
__global__ void split_kernel(const float* __restrict__ in,
                             __nv_bfloat16* __restrict__ hi,
                             __nv_bfloat16* __restrict__ lo, int n4)
{
    int i = blockIdx.x * blockDim.x + threadIdx.x;
    if (i >= n4) return;
    float4 v = *(const float4*)(in + (size_t)i * 4);
    __nv_bfloat16 h0 = __float2bfloat16(v.x);
    __nv_bfloat16 h1 = __float2bfloat16(v.y);
    __nv_bfloat16 h2 = __float2bfloat16(v.z);
    __nv_bfloat16 h3 = __float2bfloat16(v.w);
    __nv_bfloat16 l0 = __float2bfloat16(v.x - __bfloat162float(h0));
    __nv_bfloat16 l1 = __float2bfloat16(v.y - __bfloat162float(h1));
    __nv_bfloat16 l2 = __float2bfloat16(v.z - __bfloat162float(h2));
    __nv_bfloat16 l3 = __float2bfloat16(v.w - __bfloat162float(h3));
    ((__nv_bfloat162*)hi)[i * 2]     = __nv_bfloat162(h0, h1);
    ((__nv_bfloat162*)hi)[i * 2 + 1] = __nv_bfloat162(h2, h3);
    ((__nv_bfloat162*)lo)[i * 2]     = __nv_bfloat162(l0, l1);
    ((__nv_bfloat162*)lo)[i * 2 + 1] = __nv_bfloat162(l2, l3);
}

// ---------------------------------------------------------------------------
// mma.sync GEMM: C[M,N] (fp32) = Ah@Bh^T + Ah@Bl^T + Al@Bh^T  (bf16, K-major)
// 128x128 CTA tile, BK=32, 3-stage cp.async pipeline, 8 warps (2x4),
// warp tile 64x32 = 4x4 m16n8k16 tiles.
// ---------------------------------------------------------------------------
#define LDA   40                      // bf16 per smem row (80B, conflict-free)
#define STAGE_BYTES (2 * 128 * LDA * 2)   // A + B tiles = 20480
#define GEMM_SMEM (3 * STAGE_BYTES)       // 61440

__device__ __forceinline__ void gemm_copy_stage(
    const __nv_bfloat16* __restrict__ Ap, const __nv_bfloat16* __restrict__ Bp,
    int K, int m0, int n0, int kk, uint32_t sA, uint32_t sB, int tid)
{
    // Each of 256 threads copies a 32B half-row (two 16B chunks) of A and B.
    // Tile = 128 rows x 32 bf16 (64B) per operand.
    int row = tid >> 1;
    int cc  = (tid & 1) * 16;   // bf16 offset: 0 or 16
    uint32_t da = sA + (uint32_t)(row * LDA + cc) * 2;
    const void* ga0 = Ap + (size_t)(m0 + row) * K + kk + cc;
    const void* ga1 = Ap + (size_t)(m0 + row) * K + kk + cc + 8;
    asm volatile("cp.async.cg.shared.global [%0], [%1], 16;" :: "r"(da), "l"(ga0));
    asm volatile("cp.async.cg.shared.global [%0], [%1], 16;"
                 :: "r"(da + 16), "l"(ga1));
    uint32_t db = sB + (uint32_t)(row * LDA + cc) * 2;
    const void* gb0 = Bp + (size_t)(n0 + row) * K + kk + cc;
    const void* gb1 = Bp + (size_t)(n0 + row) * K + kk + cc + 8;
    asm volatile("cp.async.cg.shared.global [%0], [%1], 16;" :: "r"(db), "l"(gb0));
    asm volatile("cp.async.cg.shared.global [%0], [%1], 16;"
                 :: "r"(db + 16), "l"(gb1));
}

__global__ __launch_bounds__(256) void gemm_mma(
    const __nv_bfloat16* __restrict__ Ah, const __nv_bfloat16* __restrict__ Al,
    const __nv_bfloat16* __restrict__ Bh, const __nv_bfloat16* __restrict__ Bl,
    float* __restrict__ C, int M, int N, int K)
{
    extern __shared__ char dsm[];
    const uint32_t sb = smem_u32(dsm);
    const int tid  = threadIdx.x;
    const int wid  = tid >> 5;
    const int lane = tid & 31;
    const int wm = wid >> 2;       // 0..1
    const int wn = wid & 3;        // 0..3
    const int m0 = blockIdx.y * 128;
    const int n0 = blockIdx.x * 128;

    const int KPT  = K >> 5;       // BK=32 tiles per term
    const int n_it = 3 * KPT;

    float acc[4][4][4];
#pragma unroll
    for (int mi = 0; mi < 4; mi++)
#pragma unroll
        for (int ni = 0; ni < 4; ni++)
#pragma unroll
            for (int q = 0; q < 4; q++) acc[mi][ni][q] = 0.0f;

    // ldmatrix lane addressing
    const int a_lrow = wm * 64 + ((lane & 15));
    const int a_koff = (lane >> 4) * 8;
    const int b_g    = lane >> 3;
    const int b_nrow = wn * 32 + (lane & 7) + ((b_g >> 1) * 8);
    const int b_koff = (b_g & 1) * 8;

    // Prologue: issue stages 0,1 (both term 0)
#pragma unroll
    for (int s = 0; s < 2; s++) {
        uint32_t st = sb + s * STAGE_BYTES;
        gemm_copy_stage(Ah, Bh, K, m0, n0, s * 32, st, st + STAGE_BYTES / 2, tid);
        asm volatile("cp.async.commit_group;" ::: "memory");
    }

#pragma unroll 1
    for (int it = 0; it < n_it; it++) {
        asm volatile("cp.async.wait_group 1;" ::: "memory");
        __syncthreads();

        // issue copy for it+2
        {
            int nx = it + 2;
            if (nx < n_it) {
                int term = nx / KPT;
                int kk   = (nx - term * KPT) << 5;
                const __nv_bfloat16* Ap = (term == 2) ? Al : Ah;
                const __nv_bfloat16* Bp = (term == 1) ? Bl : Bh;
                int slot = nx % 3;
                uint32_t st = sb + slot * STAGE_BYTES;
                gemm_copy_stage(Ap, Bp, K, m0, n0, kk, st, st + STAGE_BYTES / 2, tid);
            }
            asm volatile("cp.async.commit_group;" ::: "memory");
        }

        // compute on stage it%3
        const uint32_t sA = sb + (it % 3) * STAGE_BYTES;
        const uint32_t sB = sA + STAGE_BYTES / 2;

#pragma unroll
        for (int ks = 0; ks < 2; ks++) {
            const int koff = ks * 16;
            uint32_t af[4][4], bf[4][2];
#pragma unroll
            for (int mi = 0; mi < 4; mi++) {
                uint32_t addr =
                    sA + (uint32_t)((a_lrow + mi * 16) * LDA + koff + a_koff) * 2;
                asm volatile(
                    "ldmatrix.sync.aligned.m8n8.x4.shared.b16 {%0,%1,%2,%3}, [%4];"
                    : "=r"(af[mi][0]), "=r"(af[mi][1]), "=r"(af[mi][2]),
                      "=r"(af[mi][3])
                    : "r"(addr));
            }
#pragma unroll
            for (int p = 0; p < 2; p++) {
                uint32_t addr =
                    sB + (uint32_t)((b_nrow + p * 16) * LDA + koff + b_koff) * 2;
                asm volatile(
                    "ldmatrix.sync.aligned.m8n8.x4.shared.b16 {%0,%1,%2,%3}, [%4];"
                    : "=r"(bf[2 * p][0]), "=r"(bf[2 * p][1]),
                      "=r"(bf[2 * p + 1][0]), "=r"(bf[2 * p + 1][1])
                    : "r"(addr));
            }
#pragma unroll
            for (int mi = 0; mi < 4; mi++)
#pragma unroll
                for (int ni = 0; ni < 4; ni++)
                    mma16816(acc[mi][ni], af[mi], bf[ni]);
        }
    }

    // Epilogue
#pragma unroll
    for (int mi = 0; mi < 4; mi++) {
        int row = m0 + wm * 64 + mi * 16 + (lane >> 2);
#pragma unroll
        for (int ni = 0; ni < 4; ni++) {
            int col = n0 + wn * 32 + ni * 8 + (lane & 3) * 2;
            *(float2*)(C + (size_t)row * N + col) =
                make_float2(acc[mi][ni][0], acc[mi][ni][1]);
            *(float2*)(C + (size_t)(row + 8) * N + col) =
                make_float2(acc[mi][ni][2], acc[mi][ni][3]);
        }
    }
}

// ---------------------------------------------------------------------------
// RoPE, in place. x layout: (b, s, nh, HD). total = B*S*nh*64 pair-ids.
// ---------------------------------------------------------------------------
__global__ void rope_kernel(float* __restrict__ x, const float* __restrict__ fc,
                            const float* __restrict__ fs, int nh, int total)
{
    int idx = blockIdx.x * blockDim.x + threadIdx.x;
    if (idx >= total) return;
    int i  = idx & 63;
    int th = idx >> 6;
    int s  = (th / nh) % SS;
    float c  = fc[s * 64 + i];
    float sn = fs[s * 64 + i];
    float* p = x + (size_t)th * HDD + 2 * i;
    float xr = p[0], xi = p[1];
    p[0] = xr * c - xi * sn;
    p[1] = xr * sn + xi * c;
}

// ---------------------------------------------------------------------------
// Flash attention (causal, GQA). 64 q-rows per CTA, 256 threads. (fp32 SIMT)
// ---------------------------------------------------------------------------
#define FLASH_SMEM ((128 * 68 + 128 * 68 + 64 * 128 + 64 * 68) * 4)

__global__ __launch_bounds__(256) void flash_kernel()
{
    extern __shared__ float sm[];
    float* Qt = sm;                  // [128][68]
    float* Kt = Qt + 128 * 68;       // [128][68]
    float* Vs = Kt + 128 * 68;       // [64][128]
    float* Ps = Vs + 64 * 128;       // [64][68]

    const int tid = threadIdx.x;
    const int tx = tid & 15;
    const int ty = tid >> 4;
    const int qt = blockIdx.x;
    const int h  = blockIdx.y;
    const int b  = blockIdx.z;
    const int hk = h >> 2;
    const int q0 = qt * 64;
    const float scale = 0.08838834764831845f;

    const float* qg = g_q + (((size_t)(b * SS + q0)) * NHH + h) * HDD;
    for (int f = tid; f < 64 * 32; f += 256) {
        int row = f >> 5;
        int d   = (f & 31) * 4;
        float4 v = *(const float4*)(qg + (size_t)row * (NHH * HDD) + d);
        Qt[(d + 0) * 68 + row] = v.x * scale;
        Qt[(d + 1) * 68 + row] = v.y * scale;
        Qt[(d + 2) * 68 + row] = v.z * scale;
        Qt[(d + 3) * 68 + row] = v.w * scale;
    }

    float m[4], l[4], o[4][8];
#pragma unroll
    for (int r = 0; r < 4; r++) {
        m[r] = -1e30f;
        l[r] = 0.0f;
#pragma unroll
        for (int c = 0; c < 8; c++) o[r][c] = 0.0f;
    }

    const float* kg = g_k + ((size_t)(b * SS) * NKVV + hk) * HDD;
    const float* vg = g_v + ((size_t)(b * SS) * NKVV + hk) * HDD;

    for (int kt = 0; kt <= qt; kt++) {
        __syncthreads();
        int k0 = kt * 64;
        for (int f = tid; f < 64 * 32; f += 256) {
            int row = f >> 5;
            int d   = (f & 31) * 4;
            float4 kv = *(const float4*)(kg + (size_t)(k0 + row) * (NKVV * HDD) + d);
            Kt[(d + 0) * 68 + row] = kv.x;
            Kt[(d + 1) * 68 + row] = kv.y;
            Kt[(d + 2) * 68 + row] = kv.z;
            Kt[(d + 3) * 68 + row] = kv.w;
            float4 vv = *(const float4*)(vg + (size_t)(k0 + row) * (NKVV * HDD) + d);
            *(float4*)&Vs[row * 128 + d] = vv;
        }
        __syncthreads();

        float s4[4][4];
#pragma unroll
        for (int r = 0; r < 4; r++)
#pragma unroll
            for (int c = 0; c < 4; c++) s4[r][c] = 0.0f;

        for (int d = 0; d < 128; d++) {
            float4 qv = *(const float4*)&Qt[d * 68 + 4 * ty];
            float4 kv = *(const float4*)&Kt[d * 68 + 4 * tx];
            float qa[4] = {qv.x, qv.y, qv.z, qv.w};
            float ka[4] = {kv.x, kv.y, kv.z, kv.w};
#pragma unroll
            for (int r = 0; r < 4; r++)
#pragma unroll
                for (int c = 0; c < 4; c++)
                    s4[r][c] = fmaf(qa[r], ka[c], s4[r][c]);
        }

        if (kt == qt) {
#pragma unroll
            for (int r = 0; r < 4; r++)
#pragma unroll
                for (int c = 0; c < 4; c++)
                    if (4 * tx + c > 4 * ty + r) s4[r][c] = -1e30f;
        }

#pragma unroll
        for (int r = 0; r < 4; r++) {
            float mx = fmaxf(fmaxf(s4[r][0], s4[r][1]), fmaxf(s4[r][2], s4[r][3]));
#pragma unroll
            for (int off = 8; off > 0; off >>= 1)
                mx = fmaxf(mx, __shfl_xor_sync(0xffffffffu, mx, off, 16));
            float mn    = fmaxf(m[r], mx);
            float alpha = __expf(m[r] - mn);
            float rs = 0.0f;
#pragma unroll
            for (int c = 0; c < 4; c++) {
                s4[r][c] = __expf(s4[r][c] - mn);
                rs += s4[r][c];
            }
#pragma unroll
            for (int off = 8; off > 0; off >>= 1)
                rs += __shfl_xor_sync(0xffffffffu, rs, off, 16);
            l[r] = l[r] * alpha + rs;
            m[r] = mn;
#pragma unroll
            for (int c = 0; c < 8; c++) o[r][c] *= alpha;
            *(float4*)&Ps[(4 * ty + r) * 68 + 4 * tx] =
                make_float4(s4[r][0], s4[r][1], s4[r][2], s4[r][3]);
        }
        __syncthreads();

        for (int j = 0; j < 64; j++) {
            float4 v0 = *(const float4*)&Vs[j * 128 + 8 * tx];
            float4 v1 = *(const float4*)&Vs[j * 128 + 8 * tx + 4];
            float va[8] = {v0.x, v0.y, v0.z, v0.w, v1.x, v1.y, v1.z, v1.w};
            float p0 = Ps[(4 * ty + 0) * 68 + j];
            float p1 = Ps[(4 * ty + 1) * 68 + j];
            float p2 = Ps[(4 * ty + 2) * 68 + j];
            float p3 = Ps[(4 * ty + 3) * 68 + j];
#pragma unroll
            for (int c = 0; c < 8; c++) {
                o[0][c] = fmaf(p0, va[c], o[0][c]);
                o[1][c] = fmaf(p1, va[c], o[1][c]);
                o[2][c] = fmaf(p2, va[c], o[2][c]);
                o[3][c] = fmaf(p3, va[c], o[3][c]);
            }
        }
    }

#pragma unroll
    for (int r = 0; r < 4; r++) {
        float inv = 1.0f / l[r];
        float* op = g_o + (((size_t)(b * SS + q0 + 4 * ty + r)) * NHH + h) * HDD + 8 * tx;
        *(float4*)op =
            make_float4(o[r][0] * inv, o[r][1] * inv, o[r][2] * inv, o[r][3] * inv);
        *(float4*)(op + 4) =
            make_float4(o[r][4] * inv, o[r][5] * inv, o[r][6] * inv, o[r][7] * inv);
    }
}

// ---------------------------------------------------------------------------
extern "C" void kernel_launch(void* const* d_in, const int* in_sizes, int n_in,
                              void* d_out, int out_size)
{
    const float* x  = (const float*)d_in[0];
    const float* wq = (const float*)d_in[1];
    const float* wk = (const float*)d_in[2];
    const float* wv = (const float*)d_in[3];
    const float* wo = (const float*)d_in[4];
    const float* fc = (const float*)d_in[5];
    const float* fs = (const float*)d_in[6];
    float* out = (float*)d_out;

    float *qp, *kp, *vp, *op;
    cudaGetSymbolAddress((void**)&qp, g_q);
    cudaGetSymbolAddress((void**)&kp, g_k);
    cudaGetSymbolAddress((void**)&vp, g_v);
    cudaGetSymbolAddress((void**)&op, g_o);
    __nv_bfloat16 *xh, *xl, *wqh, *wql, *wkh, *wkl, *wvh, *wvl, *woh, *wol, *oh, *ol;
    cudaGetSymbolAddress((void**)&xh, g_xh);
    cudaGetSymbolAddress((void**)&xl, g_xl);
    cudaGetSymbolAddress((void**)&wqh, g_wqh);
    cudaGetSymbolAddress((void**)&wql, g_wql);
    cudaGetSymbolAddress((void**)&wkh, g_wkh);
    cudaGetSymbolAddress((void**)&wkl, g_wkl);
    cudaGetSymbolAddress((void**)&wvh, g_wvh);
    cudaGetSymbolAddress((void**)&wvl, g_wvl);
    cudaGetSymbolAddress((void**)&woh, g_woh);
    cudaGetSymbolAddress((void**)&wol, g_wol);
    cudaGetSymbolAddress((void**)&oh, g_oh);
    cudaGetSymbolAddress((void**)&ol, g_ol);

    const int M = BB * SS;  // 4096
    const int NBIG = 4096 * 4096 / 4;
    const int NSM  = 1024 * 4096 / 4;

    // Split fp32 -> bf16 hi/lo
    split_kernel<<<(NBIG + 255) / 256, 256>>>(x, xh, xl, NBIG);
    split_kernel<<<(NBIG + 255) / 256, 256>>>(wq, wqh, wql, NBIG);
    split_kernel<<<(NSM + 255) / 256, 256>>>(wk, wkh, wkl, NSM);
    split_kernel<<<(NSM + 255) / 256, 256>>>(wv, wvh, wvl, NSM);
    split_kernel<<<(NBIG + 255) / 256, 256>>>(wo, woh, wol, NBIG);

    cudaFuncSetAttribute(gemm_mma, cudaFuncAttributeMaxDynamicSharedMemorySize,
                         GEMM_SMEM);

    // Projections (mma.sync / HMMA)
    gemm_mma<<<dim3(32, 32), 256, GEMM_SMEM>>>(xh, xl, wqh, wql, qp, M, 4096, DIMM);
    gemm_mma<<<dim3(8, 32), 256, GEMM_SMEM>>>(xh, xl, wkh, wkl, kp, M, 1024, DIMM);
    gemm_mma<<<dim3(8, 32), 256, GEMM_SMEM>>>(xh, xl, wvh, wvl, vp, M, 1024, DIMM);

    // RoPE
    int tq = BB * SS * NHH * 64;
    rope_kernel<<<(tq + 255) / 256, 256>>>(qp, fc, fs, NHH, tq);
    int tk = BB * SS * NKVV * 64;
    rope_kernel<<<(tk + 255) / 256, 256>>>(kp, fc, fs, NKVV, tk);

    // Flash attention (fp32 SIMT)
    cudaFuncSetAttribute(flash_kernel, cudaFuncAttributeMaxDynamicSharedMemorySize,
                         FLASH_SMEM);
    flash_kernel<<<dim3(SS / 64, NHH, BB), 256, FLASH_SMEM>>>();

    // Output projection (mma.sync)
    split_kernel<<<(NBIG + 255) / 256, 256>>>(op, oh, ol, NBIG);
    gemm_mma<<<dim3(32, 32), 256, GEMM_SMEM>>>(oh, ol, woh, wol, out, M, DIMM, DIMM);
}

// round 5
// speedup vs baseline: 2.8576x; 1.9610x over previous
#include <cuda_runtime.h>
#include <cuda_fp16.h>
#include <cstdint>

#define BB   2
#define SS   2048
#define DIMM 4096
#define NHH  32
#define NKVV 8
#define HDD  128

// ---------------------------------------------------------------------------
// Scratch (device globals; no allocation allowed)
// ---------------------------------------------------------------------------
__device__ float g_q[BB * SS * NHH * HDD];   // (b,s,h,hd) fp32
__device__ float g_k[BB * SS * NKVV * HDD];
__device__ float g_v[BB * SS * NKVV * HDD];
__device__ float g_o[BB * SS * NHH * HDD];   // attention out fp32

// fp16 split (hi/lo) buffers
__device__ __align__(16) __half g_xh[16777216];
__device__ __align__(16) __half g_xl[16777216];
__device__ __align__(16) __half g_wqh[16777216];
__device__ __align__(16) __half g_wql[16777216];
__device__ __align__(16) __half g_wkh[4194304];
__device__ __align__(16) __half g_wkl[4194304];
__device__ __align__(16) __half g_wvh[4194304];
__device__ __align__(16) __half g_wvl[4194304];
__device__ __align__(16) __half g_woh[16777216];
__device__ __align__(16) __half g_wol[16777216];
__device__ __align__(16) __half g_oh[16777216];
__device__ __align__(16) __half g_ol[16777216];
__device__ __align__(16) __half g_qh[16777216];
__device__ __align__(16) __half g_ql[16777216];
__device__ __align__(16) __half g_kh[4194304];
__device__ __align__(16) __half g_kl[4194304];
__device__ __align__(16) __half g_vh[4194304];
__device__ __align__(16) __half g_vl[4194304];

// ---------------------------------------------------------------------------
__device__ __forceinline__ uint32_t smem_u32(const void* p) {
    uint32_t a;
    asm("{ .reg .u64 t; cvta.to.shared.u64 t, %1; cvt.u32.u64 %0, t; }"
        : "=r"(a) : "l"(p));
    return a;
}

__device__ __forceinline__ void mma_f16(float* c, const uint32_t* a,
                                        const uint32_t* b) {
    asm volatile(
        "mma.sync.aligned.m16n8k16.row.col.f32.f16.f16.f32 "
        "{%0,%1,%2,%3}, {%4,%5,%6,%7}, {%8,%9}, {%0,%1,%2,%3};"
        : "+f"(c[0]), "+f"(c[1]), "+f"(c[2]), "+f"(c[3])
        : "r"(a[0]), "r"(a[1]), "r"(a[2]), "r"(a[3]), "r"(b[0]), "r"(b[1]));
}

__device__ __forceinline__ void ldsm4(uint32_t* r, uint32_t addr) {
    asm volatile(
        "ldmatrix.sync.aligned.m8n8.x4.shared.b16 {%0,%1,%2,%3}, [%4];"
        : "=r"(r[0]), "=r"(r[1]), "=r"(r[2]), "=r"(r[3]) : "r"(addr));
}
__device__ __forceinline__ void ldsm4t(uint32_t* r, uint32_t addr) {
    asm volatile(
        "ldmatrix.sync.aligned.m8n8.x4.trans.shared.b16 {%0,%1,%2,%3}, [%4];"
        : "=r"(r[0]), "=r"(r[1]), "=r"(r[2]), "=r"(r[3]) : "r"(addr));
}
#define CP_ASYNC16(dst, src) \
    asm volatile("cp.async.cg.shared.global [%0], [%1], 16;" :: "r"(dst), "l"(src))

// ---------------------------------------------------------------------------
// Split fp32 -> fp16 hi + fp16 lo (with optional scale)
// ---------------------------------------------------------------------------
__global__ void split2_kernel(const float* __restrict__ in,
                              __half* __restrict__ hi,
                              __half* __restrict__ lo, int n4, float scale)
{
    int i = blockIdx.x * blockDim.x + threadIdx.x;
    if (i >= n4) return;
    float4 v = *(const float4*)(in + (size_t)i * 4);
    v.x *= scale; v.y *= scale; v.z *= scale; v.w *= scale;
    __half h0 = __float2half_rn(v.x), h1 = __float2half_rn(v.y);
    __half h2 = __float2half_rn(v.z), h3 = __float2half_rn(v.w);
    __half l0 = __float2half_rn(v.x - __half2float(h0));
    __half l1 = __float2half_rn(v.y - __half2float(h1));
    __half l2 = __float2half_rn(v.z - __half2float(h2));
    __half l3 = __float2half_rn(v.w - __half2float(h3));
    ((__half2*)hi)[i * 2]     = __halves2half2(h0, h1);
    ((__half2*)hi)[i * 2 + 1] = __halves2half2(h2, h3);
    ((__half2*)lo)[i * 2]     = __halves2half2(l0, l1);
    ((__half2*)lo)[i * 2 + 1] = __halves2half2(l2, l3);
}

// ---------------------------------------------------------------------------
// mma.sync GEMM: C[M,N] (fp32), fp16 split inputs, K-major A[M,K], B[N,K].
// terms=2: Ah*Bh + Al*Bh.  terms=3: + Ah*Bl.
// 128x128 CTA tile, BK=32, 3-stage cp.async pipeline, 8 warps (2x4).
// ---------------------------------------------------------------------------
#define LDA   40
#define STAGE_BYTES (2 * 128 * LDA * 2)
#define GEMM_SMEM (3 * STAGE_BYTES)

__device__ __forceinline__ void gemm_copy_stage(
    const __half* __restrict__ Ap, const __half* __restrict__ Bp,
    int K, int m0, int n0, int kk, uint32_t sA, uint32_t sB, int tid)
{
    int row = tid >> 1;
    int cc  = (tid & 1) * 16;
    uint32_t da = sA + (uint32_t)(row * LDA + cc) * 2;
    const void* ga0 = Ap + (size_t)(m0 + row) * K + kk + cc;
    const void* ga1 = Ap + (size_t)(m0 + row) * K + kk + cc + 8;
    CP_ASYNC16(da, ga0);
    CP_ASYNC16(da + 16, ga1);
    uint32_t db = sB + (uint32_t)(row * LDA + cc) * 2;
    const void* gb0 = Bp + (size_t)(n0 + row) * K + kk + cc;
    const void* gb1 = Bp + (size_t)(n0 + row) * K + kk + cc + 8;
    CP_ASYNC16(db, gb0);
    CP_ASYNC16(db + 16, gb1);
}

__global__ __launch_bounds__(256) void gemm_mma(
    const __half* __restrict__ Ah, const __half* __restrict__ Al,
    const __half* __restrict__ Bh, const __half* __restrict__ Bl,
    float* __restrict__ C, int M, int N, int K, int terms)
{
    extern __shared__ char dsm[];
    const uint32_t sb = smem_u32(dsm);
    const int tid  = threadIdx.x;
    const int wid  = tid >> 5;
    const int lane = tid & 31;
    const int wm = wid >> 2;
    const int wn = wid & 3;
    const int m0 = blockIdx.y * 128;
    const int n0 = blockIdx.x * 128;

    const int KPT  = K >> 5;
    const int n_it = terms * KPT;

    float acc[4][4][4];
#pragma unroll
    for (int mi = 0; mi < 4; mi++)
#pragma unroll
        for (int ni = 0; ni < 4; ni++)
#pragma unroll
            for (int q = 0; q < 4; q++) acc[mi][ni][q] = 0.0f;

    const int a_lrow = wm * 64 + (lane & 15);
    const int a_koff = (lane >> 4) * 8;
    const int b_g    = lane >> 3;
    const int b_nrow = wn * 32 + (lane & 7) + ((b_g >> 1) * 8);
    const int b_koff = (b_g & 1) * 8;

#pragma unroll
    for (int s = 0; s < 2; s++) {
        uint32_t st = sb + s * STAGE_BYTES;
        gemm_copy_stage(Ah, Bh, K, m0, n0, s * 32, st, st + STAGE_BYTES / 2, tid);
        asm volatile("cp.async.commit_group;" ::: "memory");
    }

#pragma unroll 1
    for (int it = 0; it < n_it; it++) {
        asm volatile("cp.async.wait_group 1;" ::: "memory");
        __syncthreads();

        {
            int nx = it + 2;
            if (nx < n_it) {
                int term = nx / KPT;
                int kk   = (nx - term * KPT) << 5;
                const __half* Ap = (term == 1) ? Al : Ah;
                const __half* Bp = (term == 2) ? Bl : Bh;
                int slot = nx % 3;
                uint32_t st = sb + slot * STAGE_BYTES;
                gemm_copy_stage(Ap, Bp, K, m0, n0, kk, st, st + STAGE_BYTES / 2, tid);
            }
            asm volatile("cp.async.commit_group;" ::: "memory");
        }

        const uint32_t sA = sb + (it % 3) * STAGE_BYTES;
        const uint32_t sB = sA + STAGE_BYTES / 2;

#pragma unroll
        for (int ks = 0; ks < 2; ks++) {
            const int koff = ks * 16;
            uint32_t af[4][4], bf[4][2];
#pragma unroll
            for (int mi = 0; mi < 4; mi++)
                ldsm4(af[mi],
                      sA + (uint32_t)((a_lrow + mi * 16) * LDA + koff + a_koff) * 2);
#pragma unroll
            for (int p = 0; p < 2; p++) {
                uint32_t t[4];
                ldsm4(t, sB + (uint32_t)((b_nrow + p * 16) * LDA + koff + b_koff) * 2);
                bf[2 * p][0] = t[0]; bf[2 * p][1] = t[1];
                bf[2 * p + 1][0] = t[2]; bf[2 * p + 1][1] = t[3];
            }
#pragma unroll
            for (int mi = 0; mi < 4; mi++)
#pragma unroll
                for (int ni = 0; ni < 4; ni++)
                    mma_f16(acc[mi][ni], af[mi], bf[ni]);
        }
    }

#pragma unroll
    for (int mi = 0; mi < 4; mi++) {
        int row = m0 + wm * 64 + mi * 16 + (lane >> 2);
#pragma unroll
        for (int ni = 0; ni < 4; ni++) {
            int col = n0 + wn * 32 + ni * 8 + (lane & 3) * 2;
            *(float2*)(C + (size_t)row * N + col) =
                make_float2(acc[mi][ni][0], acc[mi][ni][1]);
            *(float2*)(C + (size_t)(row + 8) * N + col) =
                make_float2(acc[mi][ni][2], acc[mi][ni][3]);
        }
    }
}

// ---------------------------------------------------------------------------
// RoPE, in place, fp32. x layout: (b, s, nh, HD).
// ---------------------------------------------------------------------------
__global__ void rope_kernel(float* __restrict__ x, const float* __restrict__ fc,
                            const float* __restrict__ fs, int nh, int total)
{
    int idx = blockIdx.x * blockDim.x + threadIdx.x;
    if (idx >= total) return;
    int i  = idx & 63;
    int th = idx >> 6;
    int s  = (th / nh) % SS;
    float c  = fc[s * 64 + i];
    float sn = fs[s * 64 + i];
    float* p = x + (size_t)th * HDD + 2 * i;
    float xr = p[0], xi = p[1];
    p[0] = xr * c - xi * sn;
    p[1] = xr * sn + xi * c;
}

// ---------------------------------------------------------------------------
// Flash attention with mma.sync (causal, GQA), fp16 split, fp32 accum.
// CTA: 128 q-rows, one (b,h). 8 warps, warp = 16 rows. K-tile = 64 cols.
// Q pre-scaled+split in g_qh/g_ql. 3-term QK and PV.
// ---------------------------------------------------------------------------
#define LDT 136
#define FLASH_SMEM 69632   // max(Q: 2*128*136*2, KV: 4*64*136*2) = 69632

__device__ __forceinline__ uint32_t pack_p(float x, float y, float* rx, float* ry) {
    __half hx = __float2half_rn(x), hy = __float2half_rn(y);
    *rx = x - __half2float(hx);
    *ry = y - __half2float(hy);
    __half2 h2 = __halves2half2(hx, hy);
    return *(uint32_t*)&h2;
}
__device__ __forceinline__ uint32_t pack_h(float x, float y) {
    __half2 h2 = __halves2half2(__float2half_rn(x), __float2half_rn(y));
    return *(uint32_t*)&h2;
}

__global__ __launch_bounds__(256) void flash_mma()
{
    extern __shared__ char sm[];
    const uint32_t sb = smem_u32(sm);
    const int tid = threadIdx.x, lane = tid & 31, w = tid >> 5;
    const int qt = gridDim.x - 1 - blockIdx.x;   // big tiles first
    const int h = blockIdx.y, b = blockIdx.z, hk = h >> 2;
    const int q0 = qt * 128;

    const uint32_t sQh = sb, sQl = sb + 34816;
    const uint32_t sKh = sb, sKl = sb + 17408;
    const uint32_t sVh = sb + 34816, sVl = sb + 52224;

    // ---- load Q tile, build register fragments ----
    {
        const __half* qh = g_qh + ((size_t)(b * SS + q0) * NHH + h) * HDD;
        const __half* ql = g_ql + ((size_t)(b * SS + q0) * NHH + h) * HDD;
        for (int c = tid; c < 2048; c += 256) {
            int row = c >> 4, c8 = (c & 15) * 8;
            uint32_t off = (uint32_t)(row * LDT + c8) * 2;
            size_t g = (size_t)row * (NHH * HDD) + c8;
            CP_ASYNC16(sQh + off, qh + g);
            CP_ASYNC16(sQl + off, ql + g);
        }
        asm volatile("cp.async.commit_group;" ::: "memory");
        asm volatile("cp.async.wait_group 0;" ::: "memory");
        __syncthreads();
    }
    uint32_t qfh[8][4], qfl[8][4];
    {
        const int arow = w * 16 + (lane & 15);
        const int akoff = (lane >> 4) * 8;
#pragma unroll
        for (int ks = 0; ks < 8; ks++) {
            ldsm4(qfh[ks], sQh + (uint32_t)(arow * LDT + ks * 16 + akoff) * 2);
            ldsm4(qfl[ks], sQl + (uint32_t)(arow * LDT + ks * 16 + akoff) * 2);
        }
    }

    float m0 = -1e30f, m1 = -1e30f, l0 = 0.0f, l1 = 0.0f;
    float O[16][4];
#pragma unroll
    for (int i = 0; i < 16; i++)
#pragma unroll
        for (int q = 0; q < 4; q++) O[i][q] = 0.0f;

    const int bg = lane >> 3;
    const int b_nrow = (lane & 7) + ((bg >> 1) << 3);   // K ldsm (non-trans)
    const int b_koff = (bg & 1) * 8;
    const int vr   = (lane & 7) + ((bg & 1) << 3);      // V ldsm (trans)
    const int v_hd = (lane >> 4) * 8;

    const int nkt = 2 * qt + 2;
    for (int kt = 0; kt < nkt; kt++) {
        __syncthreads();   // previous tile's reads done before overwrite
        {
            size_t base = ((size_t)(b * SS + kt * 64) * NKVV + hk) * HDD;
            for (int c = tid; c < 1024; c += 256) {
                int row = c >> 4, c8 = (c & 15) * 8;
                uint32_t off = (uint32_t)(row * LDT + c8) * 2;
                size_t g = base + (size_t)row * (NKVV * HDD) + c8;
                CP_ASYNC16(sKh + off, g_kh + g);
                CP_ASYNC16(sKl + off, g_kl + g);
                CP_ASYNC16(sVh + off, g_vh + g);
                CP_ASYNC16(sVl + off, g_vl + g);
            }
            asm volatile("cp.async.commit_group;" ::: "memory");
            asm volatile("cp.async.wait_group 0;" ::: "memory");
            __syncthreads();
        }

        // ---- S = Q K^T (3-term) ----
        float S[8][4];
#pragma unroll
        for (int nt = 0; nt < 8; nt++)
#pragma unroll
            for (int q = 0; q < 4; q++) S[nt][q] = 0.0f;

#pragma unroll
        for (int ks = 0; ks < 8; ks++) {
#pragma unroll
            for (int p = 0; p < 4; p++) {
                uint32_t kb[4];
                ldsm4(kb, sKh + (uint32_t)((p * 16 + b_nrow) * LDT + ks * 16 + b_koff) * 2);
                mma_f16(S[2 * p], qfh[ks], kb);
                mma_f16(S[2 * p + 1], qfh[ks], kb + 2);
                mma_f16(S[2 * p], qfl[ks], kb);
                mma_f16(S[2 * p + 1], qfl[ks], kb + 2);
                ldsm4(kb, sKl + (uint32_t)((p * 16 + b_nrow) * LDT + ks * 16 + b_koff) * 2);
                mma_f16(S[2 * p], qfh[ks], kb);
                mma_f16(S[2 * p + 1], qfh[ks], kb + 2);
            }
        }

        // ---- causal mask (only tiles overlapping diagonal) ----
        const int r0g = q0 + w * 16 + (lane >> 2);
        const int r1g = r0g + 8;
        if (kt >= 2 * qt) {
            int cb = kt * 64 + (lane & 3) * 2;
#pragma unroll
            for (int nt = 0; nt < 8; nt++) {
                int c0 = cb + nt * 8;
                if (c0 > r0g)     S[nt][0] = -1e30f;
                if (c0 + 1 > r0g) S[nt][1] = -1e30f;
                if (c0 > r1g)     S[nt][2] = -1e30f;
                if (c0 + 1 > r1g) S[nt][3] = -1e30f;
            }
        }

        // ---- online softmax ----
        float mx0 = -1e30f, mx1 = -1e30f;
#pragma unroll
        for (int nt = 0; nt < 8; nt++) {
            mx0 = fmaxf(mx0, fmaxf(S[nt][0], S[nt][1]));
            mx1 = fmaxf(mx1, fmaxf(S[nt][2], S[nt][3]));
        }
        mx0 = fmaxf(mx0, __shfl_xor_sync(0xffffffffu, mx0, 1));
        mx0 = fmaxf(mx0, __shfl_xor_sync(0xffffffffu, mx0, 2));
        mx1 = fmaxf(mx1, __shfl_xor_sync(0xffffffffu, mx1, 1));
        mx1 = fmaxf(mx1, __shfl_xor_sync(0xffffffffu, mx1, 2));
        float mn0 = fmaxf(m0, mx0), mn1 = fmaxf(m1, mx1);
        float al0 = __expf(m0 - mn0), al1 = __expf(m1 - mn1);
        m0 = mn0; m1 = mn1;
        float rs0 = 0.0f, rs1 = 0.0f;
#pragma unroll
        for (int nt = 0; nt < 8; nt++) {
            S[nt][0] = __expf(S[nt][0] - m0);
            S[nt][1] = __expf(S[nt][1] - m0);
            S[nt][2] = __expf(S[nt][2] - m1);
            S[nt][3] = __expf(S[nt][3] - m1);
            rs0 += S[nt][0] + S[nt][1];
            rs1 += S[nt][2] + S[nt][3];
        }
        rs0 += __shfl_xor_sync(0xffffffffu, rs0, 1);
        rs0 += __shfl_xor_sync(0xffffffffu, rs0, 2);
        rs1 += __shfl_xor_sync(0xffffffffu, rs1, 1);
        rs1 += __shfl_xor_sync(0xffffffffu, rs1, 2);
        l0 = l0 * al0 + rs0;
        l1 = l1 * al1 + rs1;
#pragma unroll
        for (int i = 0; i < 16; i++) {
            O[i][0] *= al0; O[i][1] *= al0;
            O[i][2] *= al1; O[i][3] *= al1;
        }

        // ---- O += P V (3-term) ----
#pragma unroll
        for (int kp = 0; kp < 4; kp++) {
            uint32_t ph[4], pl[4];
            float rx, ry;
            ph[0] = pack_p(S[2 * kp][0], S[2 * kp][1], &rx, &ry);
            pl[0] = pack_h(rx, ry);
            ph[1] = pack_p(S[2 * kp][2], S[2 * kp][3], &rx, &ry);
            pl[1] = pack_h(rx, ry);
            ph[2] = pack_p(S[2 * kp + 1][0], S[2 * kp + 1][1], &rx, &ry);
            pl[2] = pack_h(rx, ry);
            ph[3] = pack_p(S[2 * kp + 1][2], S[2 * kp + 1][3], &rx, &ry);
            pl[3] = pack_h(rx, ry);
#pragma unroll
            for (int np = 0; np < 8; np++) {
                uint32_t vb[4];
                ldsm4t(vb, sVh + (uint32_t)((kp * 16 + vr) * LDT + np * 16 + v_hd) * 2);
                mma_f16(O[2 * np], ph, vb);
                mma_f16(O[2 * np + 1], ph, vb + 2);
                mma_f16(O[2 * np], pl, vb);
                mma_f16(O[2 * np + 1], pl, vb + 2);
                ldsm4t(vb, sVl + (uint32_t)((kp * 16 + vr) * LDT + np * 16 + v_hd) * 2);
                mma_f16(O[2 * np], ph, vb);
                mma_f16(O[2 * np + 1], ph, vb + 2);
            }
        }
    }

    // ---- normalize + store ----
    float i0 = 1.0f / l0, i1 = 1.0f / l1;
    int r0g = q0 + w * 16 + (lane >> 2);
    float* og  = g_o + ((size_t)(b * SS + r0g) * NHH + h) * HDD + (lane & 3) * 2;
    float* og1 = og + (size_t)8 * NHH * HDD;
#pragma unroll
    for (int nt = 0; nt < 16; nt++) {
        *(float2*)(og + nt * 8)  = make_float2(O[nt][0] * i0, O[nt][1] * i0);
        *(float2*)(og1 + nt * 8) = make_float2(O[nt][2] * i1, O[nt][3] * i1);
    }
}

// ---------------------------------------------------------------------------
extern "C" void kernel_launch(void* const* d_in, const int* in_sizes, int n_in,
                              void* d_out, int out_size)
{
    const float* x  = (const float*)d_in[0];
    const float* wq = (const float*)d_in[1];
    const float* wk = (const float*)d_in[2];
    const float* wv = (const float*)d_in[3];
    const float* wo = (const float*)d_in[4];
    const float* fc = (const float*)d_in[5];
    const float* fs = (const float*)d_in[6];
    float* out = (float*)d_out;

    float *qp, *kp, *vp, *op;
    cudaGetSymbolAddress((void**)&qp, g_q);
    cudaGetSymbolAddress((void**)&kp, g_k);
    cudaGetSymbolAddress((void**)&vp, g_v);
    cudaGetSymbolAddress((void**)&op, g_o);
    __half *xh, *xl, *wqh, *wql, *wkh, *wkl, *wvh, *wvl, *woh, *wol, *oh, *ol;
    __half *qh, *ql, *kh, *kl, *vh, *vl;
    cudaGetSymbolAddress((void**)&xh, g_xh);
    cudaGetSymbolAddress((void**)&xl, g_xl);
    cudaGetSymbolAddress((void**)&wqh, g_wqh);
    cudaGetSymbolAddress((void**)&wql, g_wql);
    cudaGetSymbolAddress((void**)&wkh, g_wkh);
    cudaGetSymbolAddress((void**)&wkl, g_wkl);
    cudaGetSymbolAddress((void**)&wvh, g_wvh);
    cudaGetSymbolAddress((void**)&wvl, g_wvl);
    cudaGetSymbolAddress((void**)&woh, g_woh);
    cudaGetSymbolAddress((void**)&wol, g_wol);
    cudaGetSymbolAddress((void**)&oh, g_oh);
    cudaGetSymbolAddress((void**)&ol, g_ol);
    cudaGetSymbolAddress((void**)&qh, g_qh);
    cudaGetSymbolAddress((void**)&ql, g_ql);
    cudaGetSymbolAddress((void**)&kh, g_kh);
    cudaGetSymbolAddress((void**)&kl, g_kl);
    cudaGetSymbolAddress((void**)&vh, g_vh);
    cudaGetSymbolAddress((void**)&vl, g_vl);

    const int M = BB * SS;                 // 4096
    const int NBIG = 16777216 / 4;
    const int NSM  = 4194304 / 4;
    const float qscale = 0.08838834764831845f;   // 1/sqrt(128)

    // Input splits
    split2_kernel<<<(NBIG + 255) / 256, 256>>>(x, xh, xl, NBIG, 1.0f);
    split2_kernel<<<(NBIG + 255) / 256, 256>>>(wq, wqh, wql, NBIG, 1.0f);
    split2_kernel<<<(NSM + 255) / 256, 256>>>(wk, wkh, wkl, NSM, 1.0f);
    split2_kernel<<<(NSM + 255) / 256, 256>>>(wv, wvh, wvl, NSM, 1.0f);
    split2_kernel<<<(NBIG + 255) / 256, 256>>>(wo, woh, wol, NBIG, 1.0f);

    cudaFuncSetAttribute(gemm_mma, cudaFuncAttributeMaxDynamicSharedMemorySize,
                         GEMM_SMEM);

    // Projections: Q 2-term, K/V 3-term
    gemm_mma<<<dim3(32, 32), 256, GEMM_SMEM>>>(xh, xl, wqh, wql, qp, M, 4096, DIMM, 2);
    gemm_mma<<<dim3(8, 32), 256, GEMM_SMEM>>>(xh, xl, wkh, wkl, kp, M, 1024, DIMM, 3);
    gemm_mma<<<dim3(8, 32), 256, GEMM_SMEM>>>(xh, xl, wvh, wvl, vp, M, 1024, DIMM, 3);

    // RoPE (fp32, in place)
    int tq = BB * SS * NHH * 64;
    rope_kernel<<<(tq + 255) / 256, 256>>>(qp, fc, fs, NHH, tq);
    int tk = BB * SS * NKVV * 64;
    rope_kernel<<<(tk + 255) / 256, 256>>>(kp, fc, fs, NKVV, tk);

    // Split q (scaled), k, v for the flash kernel
    split2_kernel<<<(NBIG + 255) / 256, 256>>>(qp, qh, ql, NBIG, qscale);
    split2_kernel<<<(NSM + 255) / 256, 256>>>(kp, kh, kl, NSM, 1.0f);
    split2_kernel<<<(NSM + 255) / 256, 256>>>(vp, vh, vl, NSM, 1.0f);

    // Flash attention (mma.sync)
    cudaFuncSetAttribute(flash_mma, cudaFuncAttributeMaxDynamicSharedMemorySize,
                         FLASH_SMEM);
    flash_mma<<<dim3(SS / 128, NHH, BB), 256, FLASH_SMEM>>>();

    // Output projection: 2-term
    split2_kernel<<<(NBIG + 255) / 256, 256>>>(op, oh, ol, NBIG, 1.0f);
    gemm_mma<<<dim3(32, 32), 256, GEMM_SMEM>>>(oh, ol, woh, wol, out, M, DIMM, DIMM, 2);
}

// round 6
// speedup vs baseline: 3.4053x; 1.1916x over previous
#include <cuda_runtime.h>
#include <cuda_fp16.h>
#include <cstdint>

#define BB   2
#define SS   2048
#define DIMM 4096
#define NHH  32
#define NKVV 8
#define HDD  128

// ---------------------------------------------------------------------------
// Scratch (device globals; no allocation allowed)
// ---------------------------------------------------------------------------
__device__ __align__(16) __half g_xh[16777216];
__device__ __align__(16) __half g_xl[16777216];
__device__ __align__(16) __half g_wqh[16777216];
__device__ __align__(16) __half g_wkh[4194304];
__device__ __align__(16) __half g_wvh[4194304];
__device__ __align__(16) __half g_woh[16777216];
__device__ __align__(16) __half g_qh[16777216];
__device__ __align__(16) __half g_ql[16777216];
__device__ __align__(16) __half g_kh[4194304];
__device__ __align__(16) __half g_vh[4194304];
__device__ __align__(16) __half g_oh[16777216];
__device__ __align__(16) __half g_ol[16777216];

// ---------------------------------------------------------------------------
__device__ __forceinline__ uint32_t smem_u32(const void* p) {
    uint32_t a;
    asm("{ .reg .u64 t; cvta.to.shared.u64 t, %1; cvt.u32.u64 %0, t; }"
        : "=r"(a) : "l"(p));
    return a;
}

__device__ __forceinline__ void mma_f16(float* c, const uint32_t* a,
                                        const uint32_t* b) {
    asm volatile(
        "mma.sync.aligned.m16n8k16.row.col.f32.f16.f16.f32 "
        "{%0,%1,%2,%3}, {%4,%5,%6,%7}, {%8,%9}, {%0,%1,%2,%3};"
        : "+f"(c[0]), "+f"(c[1]), "+f"(c[2]), "+f"(c[3])
        : "r"(a[0]), "r"(a[1]), "r"(a[2]), "r"(a[3]), "r"(b[0]), "r"(b[1]));
}

__device__ __forceinline__ void ldsm4(uint32_t* r, uint32_t addr) {
    asm volatile(
        "ldmatrix.sync.aligned.m8n8.x4.shared.b16 {%0,%1,%2,%3}, [%4];"
        : "=r"(r[0]), "=r"(r[1]), "=r"(r[2]), "=r"(r[3]) : "r"(addr));
}
__device__ __forceinline__ void ldsm4t(uint32_t* r, uint32_t addr) {
    asm volatile(
        "ldmatrix.sync.aligned.m8n8.x4.trans.shared.b16 {%0,%1,%2,%3}, [%4];"
        : "=r"(r[0]), "=r"(r[1]), "=r"(r[2]), "=r"(r[3]) : "r"(addr));
}
#define CP_ASYNC16(dst, src) \
    asm volatile("cp.async.cg.shared.global [%0], [%1], 16;" :: "r"(dst), "l"(src))

// ---------------------------------------------------------------------------
// Split fp32 -> fp16 hi + lo   /   fp32 -> fp16 hi only
// ---------------------------------------------------------------------------
__global__ void split2_kernel(const float* __restrict__ in,
                              __half* __restrict__ hi,
                              __half* __restrict__ lo, int n4)
{
    int i = blockIdx.x * blockDim.x + threadIdx.x;
    if (i >= n4) return;
    float4 v = *(const float4*)(in + (size_t)i * 4);
    __half h0 = __float2half_rn(v.x), h1 = __float2half_rn(v.y);
    __half h2 = __float2half_rn(v.z), h3 = __float2half_rn(v.w);
    ((__half2*)hi)[i * 2]     = __halves2half2(h0, h1);
    ((__half2*)hi)[i * 2 + 1] = __halves2half2(h2, h3);
    ((__half2*)lo)[i * 2]     = __halves2half2(
        __float2half_rn(v.x - __half2float(h0)),
        __float2half_rn(v.y - __half2float(h1)));
    ((__half2*)lo)[i * 2 + 1] = __halves2half2(
        __float2half_rn(v.z - __half2float(h2)),
        __float2half_rn(v.w - __half2float(h3)));
}

__global__ void tohalf_kernel(const float* __restrict__ in,
                              __half* __restrict__ hi, int n4)
{
    int i = blockIdx.x * blockDim.x + threadIdx.x;
    if (i >= n4) return;
    float4 v = *(const float4*)(in + (size_t)i * 4);
    ((__half2*)hi)[i * 2] =
        __halves2half2(__float2half_rn(v.x), __float2half_rn(v.y));
    ((__half2*)hi)[i * 2 + 1] =
        __halves2half2(__float2half_rn(v.z), __float2half_rn(v.w));
}

// ---------------------------------------------------------------------------
// mma.sync GEMM, fp16 split inputs, K-major A[M,K], B[N,K], 2 terms:
//   acc = Ah*B + Al*B
// Epilogue modes: 0 = fp32 C out; 1 = rope+scale+split(hi,lo); 2 = rope+hi; 3 = hi
// Two output segments (B1/H1 for n-block < n_split, else B2/H2) to merge K&V.
// 128x128 CTA tile, BK=32, 3-stage cp.async pipeline, 8 warps (2x4).
// ---------------------------------------------------------------------------
#define LDA   40
#define STAGE_BYTES (2 * 128 * LDA * 2)
#define GEMM_SMEM (3 * STAGE_BYTES)

__device__ __forceinline__ void gemm_copy_stage(
    const __half* __restrict__ Ap, const __half* __restrict__ Bp,
    int K, int m0, int n0, int kk, uint32_t sA, uint32_t sB, int tid)
{
    int row = tid >> 1;
    int cc  = (tid & 1) * 16;
    uint32_t da = sA + (uint32_t)(row * LDA + cc) * 2;
    CP_ASYNC16(da, Ap + (size_t)(m0 + row) * K + kk + cc);
    CP_ASYNC16(da + 16, Ap + (size_t)(m0 + row) * K + kk + cc + 8);
    uint32_t db = sB + (uint32_t)(row * LDA + cc) * 2;
    CP_ASYNC16(db, Bp + (size_t)(n0 + row) * K + kk + cc);
    CP_ASYNC16(db + 16, Bp + (size_t)(n0 + row) * K + kk + cc + 8);
}

__global__ __launch_bounds__(256) void gemm_mma(
    const __half* __restrict__ Ah, const __half* __restrict__ Al,
    const __half* __restrict__ B1, const __half* __restrict__ B2, int n_split,
    float* __restrict__ C, __half* __restrict__ H1, __half* __restrict__ L1,
    __half* __restrict__ H2,
    const float* __restrict__ fc, const float* __restrict__ fs,
    int M, int Nout, int K, int mode1, int mode2, float scale)
{
    extern __shared__ char dsm[];
    const uint32_t sb = smem_u32(dsm);
    const int tid  = threadIdx.x;
    const int wid  = tid >> 5;
    const int lane = tid & 31;
    const int wm = wid >> 2;
    const int wn = wid & 3;
    const int m0 = blockIdx.y * 128;

    const __half* Bp_sel = B1;
    __half* H = H1;
    __half* L = L1;
    int mode = mode1;
    int nb = blockIdx.x;
    if (nb >= n_split) { Bp_sel = B2; H = H2; L = nullptr; mode = mode2; nb -= n_split; }
    const int n0 = nb * 128;

    const int KPT  = K >> 5;
    const int n_it = 2 * KPT;

    float acc[4][4][4];
#pragma unroll
    for (int mi = 0; mi < 4; mi++)
#pragma unroll
        for (int ni = 0; ni < 4; ni++)
#pragma unroll
            for (int q = 0; q < 4; q++) acc[mi][ni][q] = 0.0f;

    const int a_lrow = wm * 64 + (lane & 15);
    const int a_koff = (lane >> 4) * 8;
    const int b_g    = lane >> 3;
    const int b_nrow = wn * 32 + (lane & 7) + ((b_g >> 1) * 8);
    const int b_koff = (b_g & 1) * 8;

#pragma unroll
    for (int s = 0; s < 2; s++) {
        uint32_t st = sb + s * STAGE_BYTES;
        gemm_copy_stage(Ah, Bp_sel, K, m0, n0, s * 32, st, st + STAGE_BYTES / 2, tid);
        asm volatile("cp.async.commit_group;" ::: "memory");
    }

#pragma unroll 1
    for (int it = 0; it < n_it; it++) {
        asm volatile("cp.async.wait_group 1;" ::: "memory");
        __syncthreads();

        {
            int nx = it + 2;
            if (nx < n_it) {
                int term = nx / KPT;
                int kk   = (nx - term * KPT) << 5;
                const __half* Ap = (term == 1) ? Al : Ah;
                uint32_t st = sb + (nx % 3) * STAGE_BYTES;
                gemm_copy_stage(Ap, Bp_sel, K, m0, n0, kk, st, st + STAGE_BYTES / 2,
                                tid);
            }
            asm volatile("cp.async.commit_group;" ::: "memory");
        }

        const uint32_t sA = sb + (it % 3) * STAGE_BYTES;
        const uint32_t sB = sA + STAGE_BYTES / 2;

#pragma unroll
        for (int ks = 0; ks < 2; ks++) {
            const int koff = ks * 16;
            uint32_t af[4][4], bf[4][2];
#pragma unroll
            for (int mi = 0; mi < 4; mi++)
                ldsm4(af[mi],
                      sA + (uint32_t)((a_lrow + mi * 16) * LDA + koff + a_koff) * 2);
#pragma unroll
            for (int p = 0; p < 2; p++) {
                uint32_t t[4];
                ldsm4(t, sB + (uint32_t)((b_nrow + p * 16) * LDA + koff + b_koff) * 2);
                bf[2 * p][0] = t[0]; bf[2 * p][1] = t[1];
                bf[2 * p + 1][0] = t[2]; bf[2 * p + 1][1] = t[3];
            }
#pragma unroll
            for (int mi = 0; mi < 4; mi++)
#pragma unroll
                for (int ni = 0; ni < 4; ni++)
                    mma_f16(acc[mi][ni], af[mi], bf[ni]);
        }
    }

    // ---- epilogue ----
    auto epi = [&](int r, int c, float x, float y) {
        if (mode != 3) {  // rope (modes 1, 2)
            int s = r & (SS - 1);
            int i = (c & (HDD - 1)) >> 1;
            float cs = fc[s * 64 + i], sn = fs[s * 64 + i];
            float xr = x * cs - y * sn;
            float xi = x * sn + y * cs;
            x = xr * scale;
            y = xi * scale;
        }
        __half hx = __float2half_rn(x), hy = __float2half_rn(y);
        size_t idx = (size_t)r * Nout + c;
        *(__half2*)(H + idx) = __halves2half2(hx, hy);
        if (mode == 1)
            *(__half2*)(L + idx) = __halves2half2(
                __float2half_rn(x - __half2float(hx)),
                __float2half_rn(y - __half2float(hy)));
    };

#pragma unroll
    for (int mi = 0; mi < 4; mi++) {
        int row = m0 + wm * 64 + mi * 16 + (lane >> 2);
#pragma unroll
        for (int ni = 0; ni < 4; ni++) {
            int col = n0 + wn * 32 + ni * 8 + (lane & 3) * 2;
            if (mode == 0) {
                *(float2*)(C + (size_t)row * Nout + col) =
                    make_float2(acc[mi][ni][0], acc[mi][ni][1]);
                *(float2*)(C + (size_t)(row + 8) * Nout + col) =
                    make_float2(acc[mi][ni][2], acc[mi][ni][3]);
            } else {
                epi(row, col, acc[mi][ni][0], acc[mi][ni][1]);
                epi(row + 8, col, acc[mi][ni][2], acc[mi][ni][3]);
            }
        }
    }
}

// ---------------------------------------------------------------------------
// Flash attention, mma.sync, causal GQA. 128 q-rows/CTA, 8 warps.
// 2-term QK (Qh*Kh + Ql*Kh), 2-term PV (Ph*Vh + Pl*Vh).
// K/V double-buffered (2 x 34816 B, reusing the retired Q region).
// Epilogue writes fp16 split oh/ol.
// ---------------------------------------------------------------------------
#define LDT 136
#define KV_STAGE 34816              // (64*136*2) * 2 arrays (K + V)
#define FLASH_SMEM 69632            // Q: 2*128*136*2 = 69632 = 2 KV stages

__device__ __forceinline__ uint32_t pack_p(float x, float y, float* rx, float* ry) {
    __half hx = __float2half_rn(x), hy = __float2half_rn(y);
    *rx = x - __half2float(hx);
    *ry = y - __half2float(hy);
    __half2 h2 = __halves2half2(hx, hy);
    return *(uint32_t*)&h2;
}
__device__ __forceinline__ uint32_t pack_h(float x, float y) {
    __half2 h2 = __halves2half2(__float2half_rn(x), __float2half_rn(y));
    return *(uint32_t*)&h2;
}

__global__ __launch_bounds__(256) void flash_mma()
{
    extern __shared__ char sm[];
    const uint32_t sb = smem_u32(sm);
    const int tid = threadIdx.x, lane = tid & 31, w = tid >> 5;
    const int qt = gridDim.x - 1 - blockIdx.x;   // big tiles first
    const int h = blockIdx.y, b = blockIdx.z, hk = h >> 2;
    const int q0 = qt * 128;

    const uint32_t sQh = sb, sQl = sb + 34816;

    // ---- load Q tile, build register fragments ----
    {
        const __half* qh = g_qh + ((size_t)(b * SS + q0) * NHH + h) * HDD;
        const __half* ql = g_ql + ((size_t)(b * SS + q0) * NHH + h) * HDD;
        for (int c = tid; c < 2048; c += 256) {
            int row = c >> 4, c8 = (c & 15) * 8;
            uint32_t off = (uint32_t)(row * LDT + c8) * 2;
            size_t g = (size_t)row * (NHH * HDD) + c8;
            CP_ASYNC16(sQh + off, qh + g);
            CP_ASYNC16(sQl + off, ql + g);
        }
        asm volatile("cp.async.commit_group;" ::: "memory");
        asm volatile("cp.async.wait_group 0;" ::: "memory");
        __syncthreads();
    }
    uint32_t qfh[8][4], qfl[8][4];
    {
        const int arow = w * 16 + (lane & 15);
        const int akoff = (lane >> 4) * 8;
#pragma unroll
        for (int ks = 0; ks < 8; ks++) {
            ldsm4(qfh[ks], sQh + (uint32_t)(arow * LDT + ks * 16 + akoff) * 2);
            ldsm4(qfl[ks], sQl + (uint32_t)(arow * LDT + ks * 16 + akoff) * 2);
        }
    }
    __syncthreads();   // Q fully consumed; smem free for K/V stages

    float m0 = -1e30f, m1 = -1e30f, l0 = 0.0f, l1 = 0.0f;
    float O[16][4];
#pragma unroll
    for (int i = 0; i < 16; i++)
#pragma unroll
        for (int q = 0; q < 4; q++) O[i][q] = 0.0f;

    const int bg = lane >> 3;
    const int b_nrow = (lane & 7) + ((bg >> 1) << 3);   // K ldsm (non-trans)
    const int b_koff = (bg & 1) * 8;
    const int vr   = (lane & 7) + ((bg & 1) << 3);      // V ldsm (trans)
    const int v_hd = (lane >> 4) * 8;

    auto load_tile = [&](int kt, int stg) {
        size_t base = ((size_t)(b * SS + kt * 64) * NKVV + hk) * HDD;
        uint32_t sK = sb + stg * KV_STAGE;
        uint32_t sV = sK + 17408;
        for (int c = tid; c < 1024; c += 256) {
            int row = c >> 4, c8 = (c & 15) * 8;
            uint32_t off = (uint32_t)(row * LDT + c8) * 2;
            size_t g = base + (size_t)row * (NKVV * HDD) + c8;
            CP_ASYNC16(sK + off, g_kh + g);
            CP_ASYNC16(sV + off, g_vh + g);
        }
        asm volatile("cp.async.commit_group;" ::: "memory");
    };

    const int nkt = 2 * qt + 2;
    load_tile(0, 0);

    for (int kt = 0; kt < nkt; kt++) {
        const int cur = kt & 1;
        // all warps finished computing tile kt-1 (stage cur^1) before refill
        __syncthreads();
        if (kt + 1 < nkt) {
            load_tile(kt + 1, cur ^ 1);
            asm volatile("cp.async.wait_group 1;" ::: "memory");
        } else {
            asm volatile("cp.async.wait_group 0;" ::: "memory");
        }
        __syncthreads();   // tile kt visible to all warps

        const uint32_t sK = sb + cur * KV_STAGE;
        const uint32_t sV = sK + 17408;

        // ---- S = Q K^T (2-term) ----
        float S[8][4];
#pragma unroll
        for (int nt = 0; nt < 8; nt++)
#pragma unroll
            for (int q = 0; q < 4; q++) S[nt][q] = 0.0f;

#pragma unroll
        for (int ks = 0; ks < 8; ks++) {
#pragma unroll
            for (int p = 0; p < 4; p++) {
                uint32_t kb[4];
                ldsm4(kb, sK + (uint32_t)((p * 16 + b_nrow) * LDT + ks * 16 + b_koff) * 2);
                mma_f16(S[2 * p], qfh[ks], kb);
                mma_f16(S[2 * p + 1], qfh[ks], kb + 2);
                mma_f16(S[2 * p], qfl[ks], kb);
                mma_f16(S[2 * p + 1], qfl[ks], kb + 2);
            }
        }

        // ---- causal mask ----
        const int r0g = q0 + w * 16 + (lane >> 2);
        const int r1g = r0g + 8;
        if (kt >= 2 * qt) {
            int cb = kt * 64 + (lane & 3) * 2;
#pragma unroll
            for (int nt = 0; nt < 8; nt++) {
                int c0 = cb + nt * 8;
                if (c0 > r0g)     S[nt][0] = -1e30f;
                if (c0 + 1 > r0g) S[nt][1] = -1e30f;
                if (c0 > r1g)     S[nt][2] = -1e30f;
                if (c0 + 1 > r1g) S[nt][3] = -1e30f;
            }
        }

        // ---- online softmax ----
        float mx0 = -1e30f, mx1 = -1e30f;
#pragma unroll
        for (int nt = 0; nt < 8; nt++) {
            mx0 = fmaxf(mx0, fmaxf(S[nt][0], S[nt][1]));
            mx1 = fmaxf(mx1, fmaxf(S[nt][2], S[nt][3]));
        }
        mx0 = fmaxf(mx0, __shfl_xor_sync(0xffffffffu, mx0, 1));
        mx0 = fmaxf(mx0, __shfl_xor_sync(0xffffffffu, mx0, 2));
        mx1 = fmaxf(mx1, __shfl_xor_sync(0xffffffffu, mx1, 1));
        mx1 = fmaxf(mx1, __shfl_xor_sync(0xffffffffu, mx1, 2));
        float mn0 = fmaxf(m0, mx0), mn1 = fmaxf(m1, mx1);
        float al0 = __expf(m0 - mn0), al1 = __expf(m1 - mn1);
        m0 = mn0; m1 = mn1;
        float rs0 = 0.0f, rs1 = 0.0f;
#pragma unroll
        for (int nt = 0; nt < 8; nt++) {
            S[nt][0] = __expf(S[nt][0] - m0);
            S[nt][1] = __expf(S[nt][1] - m0);
            S[nt][2] = __expf(S[nt][2] - m1);
            S[nt][3] = __expf(S[nt][3] - m1);
            rs0 += S[nt][0] + S[nt][1];
            rs1 += S[nt][2] + S[nt][3];
        }
        rs0 += __shfl_xor_sync(0xffffffffu, rs0, 1);
        rs0 += __shfl_xor_sync(0xffffffffu, rs0, 2);
        rs1 += __shfl_xor_sync(0xffffffffu, rs1, 1);
        rs1 += __shfl_xor_sync(0xffffffffu, rs1, 2);
        l0 = l0 * al0 + rs0;
        l1 = l1 * al1 + rs1;
#pragma unroll
        for (int i = 0; i < 16; i++) {
            O[i][0] *= al0; O[i][1] *= al0;
            O[i][2] *= al1; O[i][3] *= al1;
        }

        // ---- O += P V (2-term) ----
#pragma unroll
        for (int kp = 0; kp < 4; kp++) {
            uint32_t ph[4], pl[4];
            float rx, ry;
            ph[0] = pack_p(S[2 * kp][0], S[2 * kp][1], &rx, &ry);
            pl[0] = pack_h(rx, ry);
            ph[1] = pack_p(S[2 * kp][2], S[2 * kp][3], &rx, &ry);
            pl[1] = pack_h(rx, ry);
            ph[2] = pack_p(S[2 * kp + 1][0], S[2 * kp + 1][1], &rx, &ry);
            pl[2] = pack_h(rx, ry);
            ph[3] = pack_p(S[2 * kp + 1][2], S[2 * kp + 1][3], &rx, &ry);
            pl[3] = pack_h(rx, ry);
#pragma unroll
            for (int np = 0; np < 8; np++) {
                uint32_t vb[4];
                ldsm4t(vb, sV + (uint32_t)((kp * 16 + vr) * LDT + np * 16 + v_hd) * 2);
                mma_f16(O[2 * np], ph, vb);
                mma_f16(O[2 * np + 1], ph, vb + 2);
                mma_f16(O[2 * np], pl, vb);
                mma_f16(O[2 * np + 1], pl, vb + 2);
            }
        }
    }

    // ---- normalize + split + store fp16 hi/lo ----
    float i0 = 1.0f / l0, i1 = 1.0f / l1;
    int r0g = q0 + w * 16 + (lane >> 2);
    size_t idx0 = ((size_t)(b * SS + r0g) * NHH + h) * HDD + (lane & 3) * 2;
    size_t idx1 = idx0 + (size_t)8 * NHH * HDD;
#pragma unroll
    for (int nt = 0; nt < 16; nt++) {
        float x0 = O[nt][0] * i0, y0 = O[nt][1] * i0;
        float x1 = O[nt][2] * i1, y1 = O[nt][3] * i1;
        __half hx0 = __float2half_rn(x0), hy0 = __float2half_rn(y0);
        __half hx1 = __float2half_rn(x1), hy1 = __float2half_rn(y1);
        *(__half2*)(g_oh + idx0 + nt * 8) = __halves2half2(hx0, hy0);
        *(__half2*)(g_ol + idx0 + nt * 8) = __halves2half2(
            __float2half_rn(x0 - __half2float(hx0)),
            __float2half_rn(y0 - __half2float(hy0)));
        *(__half2*)(g_oh + idx1 + nt * 8) = __halves2half2(hx1, hy1);
        *(__half2*)(g_ol + idx1 + nt * 8) = __halves2half2(
            __float2half_rn(x1 - __half2float(hx1)),
            __float2half_rn(y1 - __half2float(hy1)));
    }
}

// ---------------------------------------------------------------------------
extern "C" void kernel_launch(void* const* d_in, const int* in_sizes, int n_in,
                              void* d_out, int out_size)
{
    const float* x  = (const float*)d_in[0];
    const float* wq = (const float*)d_in[1];
    const float* wk = (const float*)d_in[2];
    const float* wv = (const float*)d_in[3];
    const float* wo = (const float*)d_in[4];
    const float* fc = (const float*)d_in[5];
    const float* fs = (const float*)d_in[6];
    float* out = (float*)d_out;

    __half *xh, *xl, *wqh, *wkh, *wvh, *woh, *qh, *ql, *kh, *vh, *oh, *ol;
    cudaGetSymbolAddress((void**)&xh, g_xh);
    cudaGetSymbolAddress((void**)&xl, g_xl);
    cudaGetSymbolAddress((void**)&wqh, g_wqh);
    cudaGetSymbolAddress((void**)&wkh, g_wkh);
    cudaGetSymbolAddress((void**)&wvh, g_wvh);
    cudaGetSymbolAddress((void**)&woh, g_woh);
    cudaGetSymbolAddress((void**)&qh, g_qh);
    cudaGetSymbolAddress((void**)&ql, g_ql);
    cudaGetSymbolAddress((void**)&kh, g_kh);
    cudaGetSymbolAddress((void**)&vh, g_vh);
    cudaGetSymbolAddress((void**)&oh, g_oh);
    cudaGetSymbolAddress((void**)&ol, g_ol);

    const int M = BB * SS;                 // 4096
    const int NBIG = 16777216 / 4;
    const int NSM  = 4194304 / 4;
    const float qscale = 0.08838834764831845f;   // 1/sqrt(128)

    // Input conversions
    split2_kernel<<<(NBIG + 255) / 256, 256>>>(x, xh, xl, NBIG);
    tohalf_kernel<<<(NBIG + 255) / 256, 256>>>(wq, wqh, NBIG);
    tohalf_kernel<<<(NSM + 255) / 256, 256>>>(wk, wkh, NSM);
    tohalf_kernel<<<(NSM + 255) / 256, 256>>>(wv, wvh, NSM);
    tohalf_kernel<<<(NBIG + 255) / 256, 256>>>(wo, woh, NBIG);

    cudaFuncSetAttribute(gemm_mma, cudaFuncAttributeMaxDynamicSharedMemorySize,
                         GEMM_SMEM);

    // Q projection: rope + qscale + split(hi,lo) fused epilogue
    gemm_mma<<<dim3(32, 32), 256, GEMM_SMEM>>>(
        xh, xl, wqh, wqh, 32, nullptr, qh, ql, nullptr, fc, fs,
        M, 4096, DIMM, 1, 1, qscale);

    // K + V projections merged: K = rope+hi (blocks 0-7), V = hi (blocks 8-15)
    gemm_mma<<<dim3(16, 32), 256, GEMM_SMEM>>>(
        xh, xl, wkh, wvh, 8, nullptr, kh, nullptr, vh, fc, fs,
        M, 1024, DIMM, 2, 3, 1.0f);

    // Flash attention (2-term, double-buffered)
    cudaFuncSetAttribute(flash_mma, cudaFuncAttributeMaxDynamicSharedMemorySize,
                         FLASH_SMEM);
    flash_mma<<<dim3(SS / 128, NHH, BB), 256, FLASH_SMEM>>>();

    // Output projection: fp32 out
    gemm_mma<<<dim3(32, 32), 256, GEMM_SMEM>>>(
        oh, ol, woh, woh, 32, out, nullptr, nullptr, nullptr, fc, fs,
        M, 4096, DIMM, 0, 0, 1.0f);
}